// round 4
// baseline (speedup 1.0000x reference)
#include <cuda_runtime.h>
#include <stdint.h>

// B=8, T=8, C=1024, F=4, N=8192
#define TT 8
#define BB 8
#define CC 1024
#define FF 4
#define NN (TT*CC)
#define TB 64                   // (t,b) pairs
#define SW 16                   // strip width (columns staged in smem)
#define JQ 16                   // column units per (t,b)
#define UNITS (TB*JQ)           // 1024 CTAs
#define STRIPS 4                // 64 cols per unit / SW
#define NTHREADS 1024
#define RG (NTHREADS/SW)        // 64 row-groups
#define KITER (CC/RG)           // 16
#define NSTRIDE2 (CC+1)         // float2 stride (8200B/row)
#define SMEM_BYTES ((SW*NSTRIDE2*2 + SW*FF + SW)*4)

// per-unit partial results [unit][i][f] : 16 MB scratch
__device__ float g_partial[(size_t)UNITS * CC * FF];

__device__ __forceinline__ uint32_t tf_rotl(uint32_t x, int d) {
    return __funnelshift_l(x, x, d);
}

// JAX threefry2x32, partitionable scheme: key=(0,42), counter=(0,e),
// 20 rounds, output = x0 ^ x1.
__device__ __forceinline__ uint32_t threefry_bits(uint32_t e) {
    const uint32_t K1 = 42u;
    const uint32_t K2 = 0x1BD11BDAu ^ 42u;
    uint32_t x0 = 0u;
    uint32_t x1 = e + K1;
#define TF_R4(a,b,c,d) \
    { x0 += x1; x1 = tf_rotl(x1,(a)) ^ x0; \
      x0 += x1; x1 = tf_rotl(x1,(b)) ^ x0; \
      x0 += x1; x1 = tf_rotl(x1,(c)) ^ x0; \
      x0 += x1; x1 = tf_rotl(x1,(d)) ^ x0; }
    TF_R4(13,15,26,6)   x0 += K1; x1 += K2 + 1u;
    TF_R4(17,29,16,24)  x0 += K2; x1 += 2u;
    TF_R4(13,15,26,6)               x1 += K1 + 3u;
    TF_R4(17,29,16,24)  x0 += K1; x1 += K2 + 4u;
    TF_R4(13,15,26,6)   x0 += K2; x1 += 5u;
#undef TF_R4
    return x0 ^ x1;
}

// -ln(u): full relative accuracy for u->1 via exact v=1-u (Sterbenz) +
// 3-term series; MUFU __logf elsewhere (abs err 1.7e-7 on result >=0.0156).
__device__ __forceinline__ float neg_log_fast(float u) {
    const float v = 1.0f - u;
    const float t = fmaf(v, 0.33333333f, 0.5f);
    const float poly = fmaf(v * v, t, v);
    const float mufu = -__logf(u);
    return (v <= 0.015625f) ? poly : mufu;
}

__device__ __forceinline__ void ffma2(unsigned long long& acc,
                                      unsigned long long a,
                                      unsigned long long b) {
    asm("fma.rn.f32x2 %0, %1, %2, %0;" : "+l"(acc) : "l"(a), "l"(b));
}

// One unit = (tb, jq): 64 columns x 1024 rows of one (t,b) weight matrix.
// num = exp(w)/(-ln u) == exp(w+g) up to the softmax-invariant scale.
// num stored as float2{nv,nv} so the f32x2 epilogue gets packed operands free.
__global__ __launch_bounds__(NTHREADS, 1)
void fused_retina_kernel(const float* __restrict__ x,
                         const float* __restrict__ w) {
    const int unit = blockIdx.x;
    const int tb = unit >> 4;
    const int jq = unit & (JQ - 1);
    const int t  = tb >> 3;
    const int b  = tb & 7;
    const int jbase = jq * (STRIPS * SW);

    extern __shared__ float smem[];
    float2* num2 = reinterpret_cast<float2*>(smem);        // [SW][NSTRIDE2]
    float*  sxs  = smem + SW * NSTRIDE2 * 2;                // [SW][FF]
    float*  csum = sxs + SW * FF;                           // [SW]

    const int tid = threadIdx.x;
    const int c   = tid & (SW - 1);       // column within strip
    const int r   = tid >> 4;             // 0..63 row group

    unsigned long long acc01 = 0ull, acc23 = 0ull;   // packed f32x2 accum
    const uint32_t ebase = ((uint32_t)tb << 20);

    for (int s = 0; s < STRIPS; ++s) {
        const int j0 = jbase + s * SW;
        if (tid < SW) csum[tid] = 0.f;
        __syncthreads();

        // ---- phase 1: hash + numerator + column partial sums ----
        const int j = j0 + c;
        const float* wcol = w + ((size_t)tb << 20) + ((size_t)r << 10) + j;
        const uint32_t e0 = ebase | ((uint32_t)r << 10) | (uint32_t)j;
        float part = 0.f;
        #pragma unroll 8
        for (int k = 0; k < KITER; ++k) {
            const int i = (k << 6) + r;
            const float ww = __ldg(wcol + ((size_t)k << 16));
            const uint32_t bits = threefry_bits(e0 + ((uint32_t)k << 16));
            // bits>>9 via IMAD.HI (FMA pipe), OR via ADD (disjoint bits)
            const uint32_t ub = __umulhi(bits, 1u << 23) + 0x3f800000u;
            const float f = __uint_as_float(ub) - 1.0f;
            const float u = fmaxf(f, 1.17549435e-38f);
            const float nv = __fdividef(__expf(ww), neg_log_fast(u));
            num2[c * NSTRIDE2 + i] = make_float2(nv, nv);
            part += nv;
        }
        atomicAdd(&csum[c], part);
        __syncthreads();

        // ---- scaled gather: sxs[j][f] = x[b, j*8+t, f] / colsum[j] ----
        if (tid < SW * FF) {
            const int cc2 = tid >> 2, ff = tid & 3;
            const int jg = j0 + cc2;
            const float gx = x[((size_t)b * NN + jg * TT + t) * FF + ff];
            sxs[tid] = gx / csum[cc2];
        }
        __syncthreads();

        // ---- phase 2: acc[f] += sum_j num[tid, j] * sxs[j][f] (f32x2) ----
        #pragma unroll
        for (int jj = 0; jj < SW; ++jj) {
            const ulonglong2 s2 =
                *reinterpret_cast<const ulonglong2*>(&sxs[jj * FF]);
            const unsigned long long nvp =
                *reinterpret_cast<const unsigned long long*>(
                    &num2[jj * NSTRIDE2 + tid]);
            ffma2(acc01, nvp, s2.x);
            ffma2(acc23, nvp, s2.y);
        }
        __syncthreads();
    }

    ulonglong2* p = reinterpret_cast<ulonglong2*>(g_partial) +
                    ((size_t)unit * CC + tid);
    *p = make_ulonglong2(acc01, acc23);
}

// Reduce JQ partials per (tb, i) and scatter: out[b, i*8+t, :] = sum
__global__ void reduce_scatter_kernel(float* __restrict__ out) {
    const int gid = blockIdx.x * blockDim.x + threadIdx.x;  // [0, TB*CC)
    const int i  = gid & (CC - 1);
    const int tb = gid >> 10;
    const int t = tb >> 3, b = tb & 7;
    const float4* pp = reinterpret_cast<const float4*>(g_partial);
    float4 a = make_float4(0.f, 0.f, 0.f, 0.f);
    #pragma unroll
    for (int q = 0; q < JQ; ++q) {
        const float4 p = pp[(size_t)(tb * JQ + q) * CC + i];
        a.x += p.x; a.y += p.y; a.z += p.z; a.w += p.w;
    }
    reinterpret_cast<float4*>(out)[(size_t)b * NN + i * TT + t] = a;
}

extern "C" void kernel_launch(void* const* d_in, const int* in_sizes, int n_in,
                              void* d_out, int out_size) {
    const float* x = (const float*)d_in[0];
    const float* w = (const float*)d_in[1];
    float* out = (float*)d_out;
    (void)in_sizes; (void)n_in; (void)out_size;

    cudaFuncSetAttribute(fused_retina_kernel,
                         cudaFuncAttributeMaxDynamicSharedMemorySize, SMEM_BYTES);
    fused_retina_kernel<<<UNITS, NTHREADS, SMEM_BYTES>>>(x, w);
    reduce_scatter_kernel<<<(TB * CC) / 256, 256>>>(out);
}

// round 5
// speedup vs baseline: 1.1365x; 1.1365x over previous
#include <cuda_runtime.h>
#include <stdint.h>

// B=8, T=8, C=1024, F=4, N=8192
#define TT 8
#define BB 8
#define CC 1024
#define FF 4
#define NN (TT*CC)
#define TB 64                  // (t,b) pairs
#define SW 32                  // strip width (columns staged in smem)
#define JQ 16                  // column units per (t,b)
#define UNITS (TB*JQ)          // 1024 CTAs
#define STRIPS 2               // 64 cols per unit / SW
#define NTHREADS 1024
#define NSTRIDE (CC+1)         // smem stride, bank-conflict-free
#define SMEM_BYTES ((SW*NSTRIDE + SW*FF + SW)*4)

// per-unit partial results [unit][i][f] : 16 MB scratch
__device__ float g_partial[(size_t)UNITS * CC * FF];

__device__ __forceinline__ uint32_t tf_rotl(uint32_t x, int d) {
    return __funnelshift_l(x, x, d);
}

// JAX threefry2x32, partitionable scheme: key=(0,42), counter=(0,e),
// 20 rounds, output = x0 ^ x1.
__device__ __forceinline__ uint32_t threefry_bits(uint32_t e) {
    const uint32_t K1 = 42u;
    const uint32_t K2 = 0x1BD11BDAu ^ 42u;
    uint32_t x0 = 0u;
    uint32_t x1 = e + K1;
#define TF_R4(a,b,c,d) \
    { x0 += x1; x1 = tf_rotl(x1,(a)) ^ x0; \
      x0 += x1; x1 = tf_rotl(x1,(b)) ^ x0; \
      x0 += x1; x1 = tf_rotl(x1,(c)) ^ x0; \
      x0 += x1; x1 = tf_rotl(x1,(d)) ^ x0; }
    TF_R4(13,15,26,6)   x0 += K1; x1 += K2 + 1u;
    TF_R4(17,29,16,24)  x0 += K2; x1 += 2u;
    TF_R4(13,15,26,6)               x1 += K1 + 3u;
    TF_R4(17,29,16,24)  x0 += K1; x1 += K2 + 4u;
    TF_R4(13,15,26,6)   x0 += K2; x1 += 5u;
#undef TF_R4
    return x0 ^ x1;
}

__device__ __forceinline__ float ex2_fast(float a) {
    float r;
    asm("ex2.approx.ftz.f32 %0, %1;" : "=f"(r) : "f"(a));
    return r;
}

// One unit = (tb, jq): 64 columns x 1024 rows of one (t,b) weight matrix.
// Per strip: num = exp(w + g) up to the softmax-invariant scale, computed as
// ex2(w*log2e - log2(-ln u)). -ln u uses exact v=1-u (Sterbenz) + 3-term
// series for u->1 (relative accuracy where it matters), MUFU lg2 elsewhere.
__global__ __launch_bounds__(NTHREADS, 1)
void fused_retina_kernel(const float* __restrict__ x,
                         const float* __restrict__ w) {
    const int unit = blockIdx.x;
    const int tb = unit >> 4;               // / JQ
    const int jq = unit & (JQ - 1);
    const int t  = tb >> 3;
    const int b  = tb & 7;
    const int jbase = jq * (STRIPS * SW);   // 64 cols per unit

    extern __shared__ float smem[];
    float* num  = smem;                     // [SW][NSTRIDE]
    float* sxs  = num + SW * NSTRIDE;       // [SW][FF], 16B aligned
    float* csum = sxs + SW * FF;            // [SW]

    const int tid = threadIdx.x;
    const int c   = tid & (SW - 1);         // column within strip == lane
    const int r   = tid >> 5;               // 0..31

    float acc[FF] = {0.f, 0.f, 0.f, 0.f};   // row i = tid
    const uint32_t ebase = ((uint32_t)tb << 20);

    for (int s = 0; s < STRIPS; ++s) {
        const int j0 = jbase + s * SW;
        if (tid < SW) csum[tid] = 0.f;
        __syncthreads();

        // ---- phase 1: hash + numerator + column partial sums ----
        const int j = j0 + c;
        const float* wcol = w + ((size_t)tb << 20) + j;
        float part = 0.f;
        #pragma unroll 8
        for (int k = 0; k < CC / 32; ++k) {
            const int i = (k << 5) + r;
            const float ww = __ldg(wcol + ((size_t)i << 10));
            const uint32_t e = ebase | ((uint32_t)i << 10) | (uint32_t)j;
            const uint32_t bits = threefry_bits(e);
            // (bits>>9)|0x3f800000 as IMAD.HI + IADD (exact, disjoint bits)
            const uint32_t ub = __umulhi(bits, 1u << 23) + 0x3f800000u;
            const float f = __uint_as_float(ub) - 1.0f;
            const float u = fmaxf(f, 1.17549435e-38f);
            // -ln u: exact series near u=1, else lg2(u) * -ln2
            const float v = 1.0f - u;
            const float poly = fmaf(v * v, fmaf(v, 0.33333333f, 0.5f), v);
            const float l2u = __log2f(u);
            const float p = (v <= 0.015625f) ? poly : (l2u * -0.69314718f);
            // nv = 2^(w*log2e - log2(p)) = exp(w)/(-ln u)
            const float nv = ex2_fast(fmaf(ww, 1.44269504f, -__log2f(p)));
            num[c * NSTRIDE + i] = nv;
            part += nv;
        }
        atomicAdd(&csum[c], part);
        __syncthreads();

        // ---- scaled gather: sxs[j][f] = x[b, j*8+t, f] / colsum[j] ----
        if (tid < SW * FF) {
            const int cc2 = tid >> 2, ff = tid & 3;
            const int jg = j0 + cc2;
            const float gx = x[((size_t)b * NN + jg * TT + t) * FF + ff];
            sxs[tid] = gx / csum[cc2];
        }
        __syncthreads();

        // ---- phase 2: acc[f] += sum_j num[tid, j] * sxs[j][f] ----
        #pragma unroll
        for (int jj = 0; jj < SW; ++jj) {
            const float4 sx4 = *reinterpret_cast<const float4*>(&sxs[jj * FF]);
            const float nv = num[jj * NSTRIDE + tid];
            acc[0] = fmaf(nv, sx4.x, acc[0]);
            acc[1] = fmaf(nv, sx4.y, acc[1]);
            acc[2] = fmaf(nv, sx4.z, acc[2]);
            acc[3] = fmaf(nv, sx4.w, acc[3]);
        }
        __syncthreads();
    }

    float4* p = reinterpret_cast<float4*>(g_partial) + ((size_t)unit * CC + tid);
    *p = make_float4(acc[0], acc[1], acc[2], acc[3]);
}

// Reduce JQ partials per (tb, i) and scatter: out[b, i*8+t, :] = sum
__global__ void reduce_scatter_kernel(float* __restrict__ out) {
    const int gid = blockIdx.x * blockDim.x + threadIdx.x;  // [0, TB*CC)
    const int i  = gid & (CC - 1);
    const int tb = gid >> 10;
    const int t = tb >> 3, b = tb & 7;
    const float4* pp = reinterpret_cast<const float4*>(g_partial);
    float4 a = make_float4(0.f, 0.f, 0.f, 0.f);
    #pragma unroll
    for (int q = 0; q < JQ; ++q) {
        const float4 p = pp[(size_t)(tb * JQ + q) * CC + i];
        a.x += p.x; a.y += p.y; a.z += p.z; a.w += p.w;
    }
    reinterpret_cast<float4*>(out)[(size_t)b * NN + i * TT + t] = a;
}

extern "C" void kernel_launch(void* const* d_in, const int* in_sizes, int n_in,
                              void* d_out, int out_size) {
    const float* x = (const float*)d_in[0];
    const float* w = (const float*)d_in[1];
    float* out = (float*)d_out;
    (void)in_sizes; (void)n_in; (void)out_size;

    cudaFuncSetAttribute(fused_retina_kernel,
                         cudaFuncAttributeMaxDynamicSharedMemorySize, SMEM_BYTES);
    fused_retina_kernel<<<UNITS, NTHREADS, SMEM_BYTES>>>(x, w);
    reduce_scatter_kernel<<<(TB * CC) / 256, 256>>>(out);
}

// round 6
// speedup vs baseline: 1.1476x; 1.0098x over previous
#include <cuda_runtime.h>
#include <stdint.h>

// B=8, T=8, C=1024, F=4, N=8192
#define TT 8
#define BB 8
#define CC 1024
#define FF 4
#define NN (TT*CC)
#define TB 64                   // (t,b) pairs
#define SW 16                   // strip width (columns staged in smem)
#define JQ 16                   // column units per (t,b)
#define UNITS (TB*JQ)           // 1024 CTAs
#define STRIPS 4                // 64 cols per unit / SW
#define NTHREADS 1024
#define RG (NTHREADS/SW)        // 64 row-groups
#define KITER (CC/RG)           // 16
#define NSTRIDE 1026            // EVEN stride: half-warps hit opposite bank parity
#define SMEM_BYTES ((SW*NSTRIDE + SW*FF + SW)*4)   // 65984 B -> 2 CTAs/SM

// per-unit partial results [unit][i][f] : 16 MB scratch
__device__ float g_partial[(size_t)UNITS * CC * FF];
// opaque 1 so ptxas keeps mad.lo as IMAD (fma pipe), not IADD3 (alu pipe)
__device__ uint32_t g_one = 1u;

__device__ __forceinline__ uint32_t tf_rotl(uint32_t x, int d) {
    return __funnelshift_l(x, x, d);
}

// a + b issued as IMAD on the FMA pipe (hash adds otherwise overload ALU pipe)
__device__ __forceinline__ uint32_t addf(uint32_t a, uint32_t one, uint32_t b) {
    uint32_t d;
    asm("mad.lo.u32 %0, %1, %2, %3;" : "=r"(d) : "r"(a), "r"(one), "r"(b));
    return d;
}

// JAX threefry2x32, partitionable scheme: key=(0,42), counter=(0,e),
// 20 rounds, output = x0 ^ x1. Adds routed to the FMA pipe via IMAD.
__device__ __forceinline__ uint32_t threefry_bits(uint32_t e, uint32_t one) {
    const uint32_t K1 = 42u;
    const uint32_t K2 = 0x1BD11BDAu ^ 42u;
    uint32_t x0 = 0u;
    uint32_t x1 = e + K1;
#define TF_R4(a,b,c,d) \
    { x0 = addf(x0, one, x1); x1 = tf_rotl(x1,(a)) ^ x0; \
      x0 = addf(x0, one, x1); x1 = tf_rotl(x1,(b)) ^ x0; \
      x0 = addf(x0, one, x1); x1 = tf_rotl(x1,(c)) ^ x0; \
      x0 = addf(x0, one, x1); x1 = tf_rotl(x1,(d)) ^ x0; }
    TF_R4(13,15,26,6)   x0 = addf(x0,one,K1); x1 = addf(x1,one,K2+1u);
    TF_R4(17,29,16,24)  x0 = addf(x0,one,K2); x1 = addf(x1,one,2u);
    TF_R4(13,15,26,6)                         x1 = addf(x1,one,K1+3u);
    TF_R4(17,29,16,24)  x0 = addf(x0,one,K1); x1 = addf(x1,one,K2+4u);
    TF_R4(13,15,26,6)   x0 = addf(x0,one,K2); x1 = addf(x1,one,5u);
#undef TF_R4
    return x0 ^ x1;
}

__device__ __forceinline__ float ex2_fast(float a) {
    float r;
    asm("ex2.approx.ftz.f32 %0, %1;" : "=f"(r) : "f"(a));
    return r;
}

// One unit = (tb, jq): 64 columns x 1024 rows of one (t,b) weight matrix.
// Per strip: num = exp(w + g) up to the softmax-invariant scale, computed as
// ex2(w*log2e - log2(-ln u)). -ln u: exact v=1-u (Sterbenz) + 3-term series
// for u->1 (relative accuracy where it matters), MUFU lg2 elsewhere.
__global__ __launch_bounds__(NTHREADS, 2)
void fused_retina_kernel(const float* __restrict__ x,
                         const float* __restrict__ w) {
    const int unit = blockIdx.x;
    const int tb = unit >> 4;
    const int jq = unit & (JQ - 1);
    const int t  = tb >> 3;
    const int b  = tb & 7;
    const int jbase = jq * (STRIPS * SW);

    extern __shared__ float smem[];
    float* num  = smem;                     // [SW][NSTRIDE]
    float* sxs  = num + SW * NSTRIDE;       // [SW][FF], 16B aligned
    float* csum = sxs + SW * FF;            // [SW]

    const int tid = threadIdx.x;
    const int c   = tid & (SW - 1);         // column within strip
    const int r   = tid >> 4;               // 0..63 row group
    const uint32_t one = g_one;

    float acc[FF] = {0.f, 0.f, 0.f, 0.f};   // row i = tid
    const uint32_t ebase = ((uint32_t)tb << 20);

    for (int s = 0; s < STRIPS; ++s) {
        const int j0 = jbase + s * SW;
        if (tid < SW) csum[tid] = 0.f;
        __syncthreads();

        // ---- phase 1: hash + numerator + column partial sums ----
        const int j = j0 + c;
        const float* wcol = w + ((size_t)tb << 20) + ((size_t)r << 10) + j;
        const uint32_t e0 = ebase | ((uint32_t)r << 10) | (uint32_t)j;
        float part = 0.f;
        #pragma unroll 4
        for (int k = 0; k < KITER; ++k) {
            const int i = (k << 6) + r;
            const float ww = __ldg(wcol + ((size_t)k << 16));
            const uint32_t bits = threefry_bits(e0 + ((uint32_t)k << 16), one);
            // (bits>>9)|0x3f800000 as IMAD.HI + IADD (exact, disjoint bits)
            const uint32_t ub = __umulhi(bits, 1u << 23) + 0x3f800000u;
            const float f = __uint_as_float(ub) - 1.0f;
            const float u = fmaxf(f, 1.17549435e-38f);
            // -ln u: exact series near u=1, else lg2(u) * -ln2
            const float v = 1.0f - u;
            const float poly = fmaf(v * v, fmaf(v, 0.33333333f, 0.5f), v);
            const float l2u = __log2f(u);
            const float p = (v <= 0.015625f) ? poly : (l2u * -0.69314718f);
            // nv = 2^(w*log2e - log2(p)) = exp(w)/(-ln u)
            const float nv = ex2_fast(fmaf(ww, 1.44269504f, -__log2f(p)));
            num[c * NSTRIDE + i] = nv;
            part += nv;
        }
        // lanes l and l^16 share a column: pre-reduce, then 16 atomics/warp
        part += __shfl_xor_sync(0xffffffffu, part, 16);
        if ((tid & 31) < SW) atomicAdd(&csum[c], part);
        __syncthreads();

        // ---- scaled gather: sxs[j][f] = x[b, j*8+t, f] / colsum[j] ----
        if (tid < SW * FF) {
            const int cc2 = tid >> 2, ff = tid & 3;
            const int jg = j0 + cc2;
            const float gx = x[((size_t)b * NN + jg * TT + t) * FF + ff];
            sxs[tid] = gx / csum[cc2];
        }
        __syncthreads();

        // ---- phase 2: acc[f] += sum_j num[tid, j] * sxs[j][f] ----
        #pragma unroll
        for (int jj = 0; jj < SW; ++jj) {
            const float4 sx4 = *reinterpret_cast<const float4*>(&sxs[jj * FF]);
            const float nv = num[jj * NSTRIDE + tid];
            acc[0] = fmaf(nv, sx4.x, acc[0]);
            acc[1] = fmaf(nv, sx4.y, acc[1]);
            acc[2] = fmaf(nv, sx4.z, acc[2]);
            acc[3] = fmaf(nv, sx4.w, acc[3]);
        }
        __syncthreads();
    }

    float4* p = reinterpret_cast<float4*>(g_partial) + ((size_t)unit * CC + tid);
    *p = make_float4(acc[0], acc[1], acc[2], acc[3]);
}

// Reduce JQ partials per (tb, i) and scatter: out[b, i*8+t, :] = sum
__global__ void reduce_scatter_kernel(float* __restrict__ out) {
    const int gid = blockIdx.x * blockDim.x + threadIdx.x;  // [0, TB*CC)
    const int i  = gid & (CC - 1);
    const int tb = gid >> 10;
    const int t = tb >> 3, b = tb & 7;
    const float4* pp = reinterpret_cast<const float4*>(g_partial);
    float4 a = make_float4(0.f, 0.f, 0.f, 0.f);
    #pragma unroll
    for (int q = 0; q < JQ; ++q) {
        const float4 p = pp[(size_t)(tb * JQ + q) * CC + i];
        a.x += p.x; a.y += p.y; a.z += p.z; a.w += p.w;
    }
    reinterpret_cast<float4*>(out)[(size_t)b * NN + i * TT + t] = a;
}

extern "C" void kernel_launch(void* const* d_in, const int* in_sizes, int n_in,
                              void* d_out, int out_size) {
    const float* x = (const float*)d_in[0];
    const float* w = (const float*)d_in[1];
    float* out = (float*)d_out;
    (void)in_sizes; (void)n_in; (void)out_size;

    cudaFuncSetAttribute(fused_retina_kernel,
                         cudaFuncAttributeMaxDynamicSharedMemorySize, SMEM_BYTES);
    fused_retina_kernel<<<UNITS, NTHREADS, SMEM_BYTES>>>(x, w);
    reduce_scatter_kernel<<<(TB * CC) / 256, 256>>>(out);
}